// round 9
// baseline (speedup 1.0000x reference)
#include <cuda_runtime.h>
#include <cuda_bf16.h>
#include <cstdint>

// ----------------------------------------------------------------------------
// PhaseLinear, 2 kernels:
//  1) convert: fp32 X,W -> bf16 hi/lo planes in __device__ scratch
//  2) fused gemm: per CTA 64x32 (b,o) block, all 4 control points, in-register
//     blend. cp.async 3-stage, ldmatrix, mma.sync bf16, 3-term hi/lo comp.
//     92KB SMEM/CTA -> 2 CTAs/SM, grid 256.
// ----------------------------------------------------------------------------

#define BATCH 1024
#define INF   512
#define OUTF  512
#define NCP   4
#define NCAT  (NCP * OUTF)          // 2048

__device__ __nv_bfloat16 g_Xh[BATCH * INF], g_Xl[BATCH * INF];   // 1 MB each
__device__ __nv_bfloat16 g_Wh[NCAT * INF],  g_Wl[NCAT * INF];    // 2 MB each

// ---------------- helpers ----------------------------------------------------
__device__ __forceinline__ uint32_t smem_u32(const void* p) {
    uint32_t a;
    asm("{ .reg .u64 t; cvta.to.shared.u64 t, %1; cvt.u32.u64 %0, t; }"
        : "=r"(a) : "l"(p));
    return a;
}
__device__ __forceinline__ void split_pair(float x, float y, uint32_t& h, uint32_t& l) {
    asm("cvt.rn.bf16x2.f32 %0, %1, %2;" : "=r"(h) : "f"(y), "f"(x));  // {hi=y, lo=x}
    float hx = __uint_as_float(h << 16);
    float hy = __uint_as_float(h & 0xFFFF0000u);
    float rx = x - hx, ry = y - hy;
    asm("cvt.rn.bf16x2.f32 %0, %1, %2;" : "=r"(l) : "f"(ry), "f"(rx));
}
__device__ __forceinline__ void mma16816(float* d, const uint32_t* a, const uint32_t* b) {
    asm volatile(
        "mma.sync.aligned.m16n8k16.row.col.f32.bf16.bf16.f32 "
        "{%0,%1,%2,%3}, {%4,%5,%6,%7}, {%8,%9}, {%0,%1,%2,%3};"
        : "+f"(d[0]), "+f"(d[1]), "+f"(d[2]), "+f"(d[3])
        : "r"(a[0]), "r"(a[1]), "r"(a[2]), "r"(a[3]), "r"(b[0]), "r"(b[1]));
}
__device__ __forceinline__ void ldsm4(uint32_t* r, uint32_t addr) {
    asm volatile("ldmatrix.sync.aligned.m8n8.x4.shared.b16 {%0,%1,%2,%3}, [%4];"
        : "=r"(r[0]), "=r"(r[1]), "=r"(r[2]), "=r"(r[3]) : "r"(addr));
}
__device__ __forceinline__ void cpasync16(uint32_t dst, const void* src) {
    asm volatile("cp.async.cg.shared.global [%0], [%1], 16;" :: "r"(dst), "l"(src));
}

// ---------------- 1) convert --------------------------------------------------
__global__ void convert_kernel(const float* __restrict__ X, const float* __restrict__ W) {
    int i = blockIdx.x * blockDim.x + threadIdx.x;     // float4 index
    const int NX = BATCH * INF / 4;                    // 131072
    const int NW = NCAT * INF / 4;                     // 262144
    float4 v; uint2* dh; uint2* dl;
    if (i < NX) {
        v = ((const float4*)X)[i];
        dh = (uint2*)g_Xh + i; dl = (uint2*)g_Xl + i;
    } else {
        int j = i - NX;
        if (j >= NW) return;
        v = ((const float4*)W)[j];
        dh = (uint2*)g_Wh + j; dl = (uint2*)g_Wl + j;
    }
    uint2 hp, lp;
    split_pair(v.x, v.y, hp.x, lp.x);
    split_pair(v.z, v.w, hp.y, lp.y);
    *dh = hp; *dl = lp;
}

// ---------------- 2) fused GEMM ------------------------------------------------
// CTA: 64(m) x 32(n), BK=32, 16 K-chunks.
// Stage layout: Ah[64x80] @0, Al @5120, then B planes (32x80 each):
//   q = 2c + (0=h,1=l)  @ 10240 + q*2560.  STAGE_B = 30720, 3 stages = 92160.
#define ROWB     80
#define A_PLANE  5120
#define B_PLANE  2560
#define B_OFF    10240
#define STAGE_B  30720
#define NSTAGE   3
#define NCHUNK   (INF / 32)    // 16
#define SMEM_DYN (NSTAGE * STAGE_B)

__global__ void __launch_bounds__(256, 2)
fused_gemm(const float* __restrict__ phase, const float* __restrict__ biases,
           float* __restrict__ out) {
    extern __shared__ __align__(128) char smem[];
    const uint32_t sbase = smem_u32(smem);
    __shared__ float coef_s[NCP][64];
    __shared__ float bias_s[NCP][32];

    const int tid  = threadIdx.x;
    const int wid  = tid >> 5;
    const int lane = tid & 31;
    const int g    = lane >> 2;
    const int t    = lane & 3;
    const int wm   = wid & 1;      // m-half: wm*32
    const int wn   = wid >> 1;     // n-eighth: wn*8
    const int mx   = blockIdx.x;   // 0..15 (64 batch rows)
    const int ny   = blockIdx.y;   // 0..15 (32 out cols)

    // ---- coef + bias tables ----
    if (tid < 64) {
        const float PI = 3.14159265358979323846f;
        float p = phase[mx * 64 + tid];
        float tt = (p < 1.5f * PI) ? (p / (1.5f * PI)) : ((p - 0.5f * PI) / (1.5f * PI));
        float t2 = tt * tt, t3 = t2 * tt;
        coef_s[0][tid] = t3 - 0.5f * t2;
        coef_s[1][tid] = 1.0f - 2.5f * t3;
        coef_s[2][tid] = 0.5f * t2 + 2.0f * t3;
        coef_s[3][tid] = -0.5f * t3;
    } else if (tid < 96) {
        int j = tid - 64;
        #pragma unroll
        for (int c = 0; c < NCP; c++)
            bias_s[c][j] = biases[c * OUTF + ny * 32 + j];
    }

    // ldmatrix lane addresses (byte offsets within a plane)
    // A (per ks): m0 rows0-7 k0-7, m1 rows8-15 k0-7, m2 rows0-7 k8-15, m3 rows8-15 k8-15
    const uint32_t a_lane = (((lane >> 3) & 1) * 8 + (lane & 7)) * ROWB
                          + (lane >> 4) * 16;
    // B (whole k32): m0 n0-7 k0-7, m1 k8-15, m2 k16-23, m3 k24-31
    const uint32_t b_lane = (lane & 7) * ROWB + (lane >> 3) * 16;

    const __nv_bfloat16* xh = g_Xh + (size_t)(mx * 64) * INF;
    const __nv_bfloat16* xl = g_Xl + (size_t)(mx * 64) * INF;

    // fill one stage for K-chunk kc: 1536 cp.async x 16B, 6 per thread
    auto fill = [&](int stage, int kc) {
        #pragma unroll
        for (int i = 0; i < 6; i++) {
            int u = i * 256 + tid;           // 0..1535
            uint32_t dst;
            const __nv_bfloat16* src;
            if (u < 512) {                   // A planes: 2 x 64 rows x 4 segs
                int pl  = u >> 8;            // 0 Ah, 1 Al
                int r   = (u >> 2) & 63;
                int seg = u & 3;
                src = (pl ? xl : xh) + (size_t)r * INF + kc * 32 + seg * 8;
                dst = sbase + stage * STAGE_B + pl * A_PLANE + r * ROWB + seg * 16;
            } else {                         // B planes: 8 x 32 rows x 4 segs
                int v   = u - 512;
                int q   = v >> 7;            // 0..7 = 2c + (h/l)
                int r   = (v >> 2) & 31;
                int seg = v & 3;
                int c   = q >> 1;
                const __nv_bfloat16* wb = (q & 1) ? g_Wl : g_Wh;
                src = wb + (size_t)(c * OUTF + ny * 32 + r) * INF + kc * 32 + seg * 8;
                dst = sbase + stage * STAGE_B + B_OFF + q * B_PLANE + r * ROWB + seg * 16;
            }
            cpasync16(dst, src);
        }
        asm volatile("cp.async.commit_group;" ::: "memory");
    };

    // accumulators: 4 control points x 2 m-frags x 4
    float acc[NCP][2][4];
    #pragma unroll
    for (int c = 0; c < NCP; c++)
        #pragma unroll
        for (int mf = 0; mf < 2; mf++)
            #pragma unroll
            for (int r = 0; r < 4; r++) acc[c][mf][r] = 0.f;

    fill(0, 0); fill(1, 1); fill(2, 2);

    for (int kc = 0; kc < NCHUNK; kc++) {
        if (kc <= NCHUNK - 4)
            asm volatile("cp.async.wait_group 2;" ::: "memory");
        else
            asm volatile("cp.async.wait_group 0;" ::: "memory");
        __syncthreads();

        const int st = kc % NSTAGE;
        const uint32_t sS = sbase + st * STAGE_B;

        // B fragments for the whole chunk: one x4 per (c, h/l)
        uint32_t bh[NCP][4], bl[NCP][4];   // [0..1]=ks0, [2..3]=ks1
        #pragma unroll
        for (int c = 0; c < NCP; c++) {
            uint32_t rb = (wn * 8) * ROWB + b_lane;
            ldsm4(bh[c], sS + B_OFF + (2 * c) * B_PLANE + rb);
            ldsm4(bl[c], sS + B_OFF + (2 * c + 1) * B_PLANE + rb);
        }

        #pragma unroll
        for (int ks = 0; ks < 2; ks++) {
            const uint32_t ko = ks * 32;
            uint32_t ah[2][4], al[2][4];
            #pragma unroll
            for (int mf = 0; mf < 2; mf++) {
                uint32_t ra = (wm * 32 + mf * 16) * ROWB + a_lane + ko;
                ldsm4(ah[mf], sS + ra);
                ldsm4(al[mf], sS + A_PLANE + ra);
            }
            #pragma unroll
            for (int c = 0; c < NCP; c++) {
                #pragma unroll
                for (int mf = 0; mf < 2; mf++) {
                    mma16816(acc[c][mf], ah[mf], &bh[c][2 * ks]);
                    mma16816(acc[c][mf], ah[mf], &bl[c][2 * ks]);
                    mma16816(acc[c][mf], al[mf], &bh[c][2 * ks]);
                }
            }
        }
        __syncthreads();
        if (kc + NSTAGE < NCHUNK) fill(st, kc + NSTAGE);
    }

    // ---- epilogue: blend with coef + bias, store 64x32 tile ----
    #pragma unroll
    for (int mf = 0; mf < 2; mf++) {
        const int rl0  = wm * 32 + mf * 16 + g;
        const int row0 = mx * 64 + rl0;
        const int cl   = wn * 8 + 2 * t;
        float r0 = 0.f, r1 = 0.f, r2 = 0.f, r3 = 0.f;
        #pragma unroll
        for (int c = 0; c < NCP; c++) {
            float cc0 = coef_s[c][rl0];
            float cc8 = coef_s[c][rl0 + 8];
            float b0  = bias_s[c][cl];
            float b1  = bias_s[c][cl + 1];
            r0 = fmaf(cc0, acc[c][mf][0] + b0, r0);
            r1 = fmaf(cc0, acc[c][mf][1] + b1, r1);
            r2 = fmaf(cc8, acc[c][mf][2] + b0, r2);
            r3 = fmaf(cc8, acc[c][mf][3] + b1, r3);
        }
        int col = ny * 32 + cl;
        *(float2*)(out + (size_t)row0 * OUTF + col)       = make_float2(r0, r1);
        *(float2*)(out + (size_t)(row0 + 8) * OUTF + col) = make_float2(r2, r3);
    }
}

// ---------------- launch -------------------------------------------------------
extern "C" void kernel_launch(void* const* d_in, const int* in_sizes, int n_in,
                              void* d_out, int out_size) {
    const float* input   = (const float*)d_in[0];   // [1024,512]
    const float* phase   = (const float*)d_in[1];   // [1024]
    const float* weights = (const float*)d_in[2];   // [4,512,512]
    const float* biases  = (const float*)d_in[3];   // [4,512]
    float* out = (float*)d_out;                     // [1024,512]

    cudaFuncSetAttribute(fused_gemm,
                         cudaFuncAttributeMaxDynamicSharedMemorySize, SMEM_DYN);

    convert_kernel<<<1536, 256>>>(input, weights);

    dim3 grid(BATCH / 64, OUTF / 32);               // (16,16) = 256 CTAs
    fused_gemm<<<grid, 256, SMEM_DYN>>>(phase, biases, out);
}

// round 10
// speedup vs baseline: 1.0137x; 1.0137x over previous
#include <cuda_runtime.h>
#include <cuda_bf16.h>
#include <cstdint>

// ----------------------------------------------------------------------------
// PhaseLinear, 2 kernels:
//  1) convert: fp32 X,W -> bf16 hi/lo planes in __device__ scratch
//  2) fused gemm: per CTA 64x32 (b,o) block, all 4 control points, in-register
//     blend. cp.async 3-stage, ldmatrix, mma.sync bf16, 3-term hi/lo comp.
//     MMA issue order (ks, term, c, mf): same-accumulator MMAs 8 apart to
//     break HMMA accumulate-dependency chains.
// ----------------------------------------------------------------------------

#define BATCH 1024
#define INF   512
#define OUTF  512
#define NCP   4
#define NCAT  (NCP * OUTF)          // 2048

__device__ __nv_bfloat16 g_Xh[BATCH * INF], g_Xl[BATCH * INF];   // 1 MB each
__device__ __nv_bfloat16 g_Wh[NCAT * INF],  g_Wl[NCAT * INF];    // 2 MB each

// ---------------- helpers ----------------------------------------------------
__device__ __forceinline__ uint32_t smem_u32(const void* p) {
    uint32_t a;
    asm("{ .reg .u64 t; cvta.to.shared.u64 t, %1; cvt.u32.u64 %0, t; }"
        : "=r"(a) : "l"(p));
    return a;
}
__device__ __forceinline__ void split_pair(float x, float y, uint32_t& h, uint32_t& l) {
    asm("cvt.rn.bf16x2.f32 %0, %1, %2;" : "=r"(h) : "f"(y), "f"(x));  // {hi=y, lo=x}
    float hx = __uint_as_float(h << 16);
    float hy = __uint_as_float(h & 0xFFFF0000u);
    float rx = x - hx, ry = y - hy;
    asm("cvt.rn.bf16x2.f32 %0, %1, %2;" : "=r"(l) : "f"(ry), "f"(rx));
}
__device__ __forceinline__ void mma16816(float* d, const uint32_t* a, const uint32_t* b) {
    asm volatile(
        "mma.sync.aligned.m16n8k16.row.col.f32.bf16.bf16.f32 "
        "{%0,%1,%2,%3}, {%4,%5,%6,%7}, {%8,%9}, {%0,%1,%2,%3};"
        : "+f"(d[0]), "+f"(d[1]), "+f"(d[2]), "+f"(d[3])
        : "r"(a[0]), "r"(a[1]), "r"(a[2]), "r"(a[3]), "r"(b[0]), "r"(b[1]));
}
__device__ __forceinline__ void ldsm4(uint32_t* r, uint32_t addr) {
    asm volatile("ldmatrix.sync.aligned.m8n8.x4.shared.b16 {%0,%1,%2,%3}, [%4];"
        : "=r"(r[0]), "=r"(r[1]), "=r"(r[2]), "=r"(r[3]) : "r"(addr));
}
__device__ __forceinline__ void cpasync16(uint32_t dst, const void* src) {
    asm volatile("cp.async.cg.shared.global [%0], [%1], 16;" :: "r"(dst), "l"(src));
}

// ---------------- 1) convert --------------------------------------------------
__global__ void convert_kernel(const float* __restrict__ X, const float* __restrict__ W) {
    int i = blockIdx.x * blockDim.x + threadIdx.x;     // float4 index
    const int NX = BATCH * INF / 4;                    // 131072
    const int NW = NCAT * INF / 4;                     // 262144
    float4 v; uint2* dh; uint2* dl;
    if (i < NX) {
        v = ((const float4*)X)[i];
        dh = (uint2*)g_Xh + i; dl = (uint2*)g_Xl + i;
    } else {
        int j = i - NX;
        if (j >= NW) return;
        v = ((const float4*)W)[j];
        dh = (uint2*)g_Wh + j; dl = (uint2*)g_Wl + j;
    }
    uint2 hp, lp;
    split_pair(v.x, v.y, hp.x, lp.x);
    split_pair(v.z, v.w, hp.y, lp.y);
    *dh = hp; *dl = lp;
}

// ---------------- 2) fused GEMM ------------------------------------------------
// CTA: 64(m) x 32(n), BK=32, 16 K-chunks.
// Stage: Ah[64x80] @0, Al @5120, B planes (32x80) q=2c+(h/l) @10240+q*2560.
#define ROWB     80
#define A_PLANE  5120
#define B_PLANE  2560
#define B_OFF    10240
#define STAGE_B  30720
#define NSTAGE   3
#define NCHUNK   (INF / 32)    // 16
#define SMEM_DYN (NSTAGE * STAGE_B)

__global__ void __launch_bounds__(256, 2)
fused_gemm(const float* __restrict__ phase, const float* __restrict__ biases,
           float* __restrict__ out) {
    extern __shared__ __align__(128) char smem[];
    const uint32_t sbase = smem_u32(smem);
    __shared__ float coef_s[NCP][64];
    __shared__ float bias_s[NCP][32];

    const int tid  = threadIdx.x;
    const int wid  = tid >> 5;
    const int lane = tid & 31;
    const int g    = lane >> 2;
    const int t    = lane & 3;
    const int wm   = wid & 1;      // m-half: wm*32
    const int wn   = wid >> 1;     // n-eighth: wn*8
    const int mx   = blockIdx.x;   // 0..15 (64 batch rows)
    const int ny   = blockIdx.y;   // 0..15 (32 out cols)

    // ---- coef + bias tables ----
    if (tid < 64) {
        const float PI = 3.14159265358979323846f;
        float p = phase[mx * 64 + tid];
        float tt = (p < 1.5f * PI) ? (p / (1.5f * PI)) : ((p - 0.5f * PI) / (1.5f * PI));
        float t2 = tt * tt, t3 = t2 * tt;
        coef_s[0][tid] = t3 - 0.5f * t2;
        coef_s[1][tid] = 1.0f - 2.5f * t3;
        coef_s[2][tid] = 0.5f * t2 + 2.0f * t3;
        coef_s[3][tid] = -0.5f * t3;
    } else if (tid < 96) {
        int j = tid - 64;
        #pragma unroll
        for (int c = 0; c < NCP; c++)
            bias_s[c][j] = biases[c * OUTF + ny * 32 + j];
    }

    // ldmatrix lane addresses (byte offsets within a plane)
    const uint32_t a_lane = (((lane >> 3) & 1) * 8 + (lane & 7)) * ROWB
                          + (lane >> 4) * 16;
    const uint32_t b_lane = (lane & 7) * ROWB + (lane >> 3) * 16;

    const __nv_bfloat16* xh = g_Xh + (size_t)(mx * 64) * INF;
    const __nv_bfloat16* xl = g_Xl + (size_t)(mx * 64) * INF;

    // fill one stage for K-chunk kc: 1536 cp.async x 16B, 6 per thread
    auto fill = [&](int stage, int kc) {
        #pragma unroll
        for (int i = 0; i < 6; i++) {
            int u = i * 256 + tid;           // 0..1535
            uint32_t dst;
            const __nv_bfloat16* src;
            if (u < 512) {                   // A planes
                int pl  = u >> 8;            // 0 Ah, 1 Al
                int r   = (u >> 2) & 63;
                int seg = u & 3;
                src = (pl ? xl : xh) + (size_t)r * INF + kc * 32 + seg * 8;
                dst = sbase + stage * STAGE_B + pl * A_PLANE + r * ROWB + seg * 16;
            } else {                         // B planes
                int v   = u - 512;
                int q   = v >> 7;            // 0..7 = 2c + (h/l)
                int r   = (v >> 2) & 31;
                int seg = v & 3;
                int c   = q >> 1;
                const __nv_bfloat16* wb = (q & 1) ? g_Wl : g_Wh;
                src = wb + (size_t)(c * OUTF + ny * 32 + r) * INF + kc * 32 + seg * 8;
                dst = sbase + stage * STAGE_B + B_OFF + q * B_PLANE + r * ROWB + seg * 16;
            }
            cpasync16(dst, src);
        }
        asm volatile("cp.async.commit_group;" ::: "memory");
    };

    // accumulators: 4 control points x 2 m-frags x 4
    float acc[NCP][2][4];
    #pragma unroll
    for (int c = 0; c < NCP; c++)
        #pragma unroll
        for (int mf = 0; mf < 2; mf++)
            #pragma unroll
            for (int r = 0; r < 4; r++) acc[c][mf][r] = 0.f;

    fill(0, 0); fill(1, 1); fill(2, 2);

    for (int kc = 0; kc < NCHUNK; kc++) {
        if (kc <= NCHUNK - 4)
            asm volatile("cp.async.wait_group 2;" ::: "memory");
        else
            asm volatile("cp.async.wait_group 0;" ::: "memory");
        __syncthreads();

        const int st = kc % NSTAGE;
        const uint32_t sS = sbase + st * STAGE_B;

        // --- load ALL fragments for this chunk up front ---
        uint32_t bh[NCP][4], bl[NCP][4];      // [2*ks + 0..1]
        #pragma unroll
        for (int c = 0; c < NCP; c++) {
            uint32_t rb = (wn * 8) * ROWB + b_lane;
            ldsm4(bh[c], sS + B_OFF + (2 * c) * B_PLANE + rb);
            ldsm4(bl[c], sS + B_OFF + (2 * c + 1) * B_PLANE + rb);
        }
        uint32_t ah[2][2][4], al[2][2][4];    // [ks][mf]
        #pragma unroll
        for (int ks = 0; ks < 2; ks++) {
            #pragma unroll
            for (int mf = 0; mf < 2; mf++) {
                uint32_t ra = (wm * 32 + mf * 16) * ROWB + a_lane + ks * 32;
                ldsm4(ah[ks][mf], sS + ra);
                ldsm4(al[ks][mf], sS + A_PLANE + ra);
            }
        }

        // --- MMA: order (ks, term, c, mf) -> same-acc distance = 8 MMAs ---
        #pragma unroll
        for (int ks = 0; ks < 2; ks++) {
            #pragma unroll
            for (int term = 0; term < 3; term++) {
                #pragma unroll
                for (int c = 0; c < NCP; c++) {
                    #pragma unroll
                    for (int mf = 0; mf < 2; mf++) {
                        const uint32_t* af = (term == 2) ? al[ks][mf] : ah[ks][mf];
                        const uint32_t* bf = (term == 1) ? &bl[c][2 * ks]
                                                         : &bh[c][2 * ks];
                        mma16816(acc[c][mf], af, bf);
                    }
                }
            }
        }
        __syncthreads();
        if (kc + NSTAGE < NCHUNK) fill(st, kc + NSTAGE);
    }

    // ---- epilogue: blend with coef + bias, store 64x32 tile ----
    #pragma unroll
    for (int mf = 0; mf < 2; mf++) {
        const int rl0  = wm * 32 + mf * 16 + g;
        const int row0 = mx * 64 + rl0;
        const int cl   = wn * 8 + 2 * t;
        float r0 = 0.f, r1 = 0.f, r2 = 0.f, r3 = 0.f;
        #pragma unroll
        for (int c = 0; c < NCP; c++) {
            float cc0 = coef_s[c][rl0];
            float cc8 = coef_s[c][rl0 + 8];
            float b0  = bias_s[c][cl];
            float b1  = bias_s[c][cl + 1];
            r0 = fmaf(cc0, acc[c][mf][0] + b0, r0);
            r1 = fmaf(cc0, acc[c][mf][1] + b1, r1);
            r2 = fmaf(cc8, acc[c][mf][2] + b0, r2);
            r3 = fmaf(cc8, acc[c][mf][3] + b1, r3);
        }
        int col = ny * 32 + cl;
        *(float2*)(out + (size_t)row0 * OUTF + col)       = make_float2(r0, r1);
        *(float2*)(out + (size_t)(row0 + 8) * OUTF + col) = make_float2(r2, r3);
    }
}

// ---------------- launch -------------------------------------------------------
extern "C" void kernel_launch(void* const* d_in, const int* in_sizes, int n_in,
                              void* d_out, int out_size) {
    const float* input   = (const float*)d_in[0];   // [1024,512]
    const float* phase   = (const float*)d_in[1];   // [1024]
    const float* weights = (const float*)d_in[2];   // [4,512,512]
    const float* biases  = (const float*)d_in[3];   // [4,512]
    float* out = (float*)d_out;                     // [1024,512]

    cudaFuncSetAttribute(fused_gemm,
                         cudaFuncAttributeMaxDynamicSharedMemorySize, SMEM_DYN);

    convert_kernel<<<1536, 256>>>(input, weights);

    dim3 grid(BATCH / 64, OUTF / 32);               // (16,16) = 256 CTAs
    fused_gemm<<<grid, 256, SMEM_DYN>>>(phase, biases, out);
}

// round 11
// speedup vs baseline: 1.2193x; 1.2029x over previous
#include <cuda_runtime.h>
#include <cuda_bf16.h>
#include <cstdint>

// ----------------------------------------------------------------------------
// PhaseLinear, 2 kernels:
//  1) convert: fp32 X,W -> bf16 hi/lo planes in __device__ scratch
//  2) fused gemm: per CTA 64x32 (b,o) block, all 4 control points, in-register
//     blend. BK=64, 2-stage cp.async double buffer, ONE barrier per chunk,
//     fill issued right after the barrier so loads overlap the MMA block.
//     mma.sync bf16 3-term hi/lo compensation.
// ----------------------------------------------------------------------------

#define BATCH 1024
#define INF   512
#define OUTF  512
#define NCP   4
#define NCAT  (NCP * OUTF)          // 2048

__device__ __nv_bfloat16 g_Xh[BATCH * INF], g_Xl[BATCH * INF];   // 1 MB each
__device__ __nv_bfloat16 g_Wh[NCAT * INF],  g_Wl[NCAT * INF];    // 2 MB each

// ---------------- helpers ----------------------------------------------------
__device__ __forceinline__ uint32_t smem_u32(const void* p) {
    uint32_t a;
    asm("{ .reg .u64 t; cvta.to.shared.u64 t, %1; cvt.u32.u64 %0, t; }"
        : "=r"(a) : "l"(p));
    return a;
}
__device__ __forceinline__ void split_pair(float x, float y, uint32_t& h, uint32_t& l) {
    asm("cvt.rn.bf16x2.f32 %0, %1, %2;" : "=r"(h) : "f"(y), "f"(x));  // {hi=y, lo=x}
    float hx = __uint_as_float(h << 16);
    float hy = __uint_as_float(h & 0xFFFF0000u);
    float rx = x - hx, ry = y - hy;
    asm("cvt.rn.bf16x2.f32 %0, %1, %2;" : "=r"(l) : "f"(ry), "f"(rx));
}
__device__ __forceinline__ void mma16816(float* d, const uint32_t* a, const uint32_t* b) {
    asm volatile(
        "mma.sync.aligned.m16n8k16.row.col.f32.bf16.bf16.f32 "
        "{%0,%1,%2,%3}, {%4,%5,%6,%7}, {%8,%9}, {%0,%1,%2,%3};"
        : "+f"(d[0]), "+f"(d[1]), "+f"(d[2]), "+f"(d[3])
        : "r"(a[0]), "r"(a[1]), "r"(a[2]), "r"(a[3]), "r"(b[0]), "r"(b[1]));
}
__device__ __forceinline__ void ldsm4(uint32_t* r, uint32_t addr) {
    asm volatile("ldmatrix.sync.aligned.m8n8.x4.shared.b16 {%0,%1,%2,%3}, [%4];"
        : "=r"(r[0]), "=r"(r[1]), "=r"(r[2]), "=r"(r[3]) : "r"(addr));
}
__device__ __forceinline__ void cpasync16(uint32_t dst, const void* src) {
    asm volatile("cp.async.cg.shared.global [%0], [%1], 16;" :: "r"(dst), "l"(src));
}

// ---------------- 1) convert --------------------------------------------------
__global__ void convert_kernel(const float* __restrict__ X, const float* __restrict__ W) {
    int i = blockIdx.x * blockDim.x + threadIdx.x;     // float4 index
    const int NX = BATCH * INF / 4;                    // 131072
    const int NW = NCAT * INF / 4;                     // 262144
    float4 v; uint2* dh; uint2* dl;
    if (i < NX) {
        v = ((const float4*)X)[i];
        dh = (uint2*)g_Xh + i; dl = (uint2*)g_Xl + i;
    } else {
        int j = i - NX;
        if (j >= NW) return;
        v = ((const float4*)W)[j];
        dh = (uint2*)g_Wh + j; dl = (uint2*)g_Wl + j;
    }
    uint2 hp, lp;
    split_pair(v.x, v.y, hp.x, lp.x);
    split_pair(v.z, v.w, hp.y, lp.y);
    *dh = hp; *dl = lp;
}

// ---------------- 2) fused GEMM ------------------------------------------------
// CTA: 64(m) x 32(n), BK=64, 8 K-chunks, 2 stages.
// Stage: Ah[64x144B] @0, Al @9216, B planes (32x144B) q=2c+(h/l) @18432+q*4608.
#define ROWB     144
#define A_PLANE  9216
#define B_PLANE  4608
#define B_OFF    18432
#define STAGE_B  55296
#define NCHUNK   (INF / 64)    // 8
#define SMEM_DYN (2 * STAGE_B) // 110592

__global__ void __launch_bounds__(256, 2)
fused_gemm(const float* __restrict__ phase, const float* __restrict__ biases,
           float* __restrict__ out) {
    extern __shared__ __align__(128) char smem[];
    const uint32_t sbase = smem_u32(smem);
    __shared__ float coef_s[NCP][64];
    __shared__ float bias_s[NCP][32];

    const int tid  = threadIdx.x;
    const int wid  = tid >> 5;
    const int lane = tid & 31;
    const int g    = lane >> 2;
    const int t    = lane & 3;
    const int wm   = wid & 1;      // m-half: wm*32
    const int wn   = wid >> 1;     // n-eighth: wn*8
    const int mx   = blockIdx.x;   // 0..15 (64 batch rows)
    const int ny   = blockIdx.y;   // 0..15 (32 out cols)

    // ---- coef + bias tables ----
    if (tid < 64) {
        const float PI = 3.14159265358979323846f;
        float p = phase[mx * 64 + tid];
        float tt = (p < 1.5f * PI) ? (p / (1.5f * PI)) : ((p - 0.5f * PI) / (1.5f * PI));
        float t2 = tt * tt, t3 = t2 * tt;
        coef_s[0][tid] = t3 - 0.5f * t2;
        coef_s[1][tid] = 1.0f - 2.5f * t3;
        coef_s[2][tid] = 0.5f * t2 + 2.0f * t3;
        coef_s[3][tid] = -0.5f * t3;
    } else if (tid < 96) {
        int j = tid - 64;
        #pragma unroll
        for (int c = 0; c < NCP; c++)
            bias_s[c][j] = biases[c * OUTF + ny * 32 + j];
    }

    // ldmatrix lane addresses (byte offsets within a plane).
    // ROWB=144 -> 36 words; 36 ≡ 4 (mod 32): 8 consecutive rows hit 8 distinct
    // 16B-groups covering all banks -> conflict-free ldmatrix phases.
    const uint32_t a_lane = (((lane >> 3) & 1) * 8 + (lane & 7)) * ROWB
                          + (lane >> 4) * 16;
    const uint32_t b_lane = (lane & 7) * ROWB + (lane >> 3) * 16;   // x4 spans k32

    const __nv_bfloat16* xh = g_Xh + (size_t)(mx * 64) * INF;
    const __nv_bfloat16* xl = g_Xl + (size_t)(mx * 64) * INF;

    // fill one stage for K-chunk kc: 3072 cp.async x 16B, 12 per thread
    auto fill = [&](int stage, int kc) {
        #pragma unroll
        for (int i = 0; i < 12; i++) {
            int u = i * 256 + tid;           // 0..3071
            uint32_t dst;
            const __nv_bfloat16* src;
            if (u < 1024) {                  // A planes: 2 x 64 rows x 8 segs
                int pl  = u >> 9;            // 0 Ah, 1 Al
                int r   = (u >> 3) & 63;
                int seg = u & 7;
                src = (pl ? xl : xh) + (size_t)r * INF + kc * 64 + seg * 8;
                dst = sbase + stage * STAGE_B + pl * A_PLANE + r * ROWB + seg * 16;
            } else {                         // B planes: 8 x 32 rows x 8 segs
                int v   = u - 1024;
                int q   = v >> 8;            // 0..7 = 2c + (h/l)
                int r   = (v >> 3) & 31;
                int seg = v & 7;
                int c   = q >> 1;
                const __nv_bfloat16* wb = (q & 1) ? g_Wl : g_Wh;
                src = wb + (size_t)(c * OUTF + ny * 32 + r) * INF + kc * 64 + seg * 8;
                dst = sbase + stage * STAGE_B + B_OFF + q * B_PLANE + r * ROWB + seg * 16;
            }
            cpasync16(dst, src);
        }
        asm volatile("cp.async.commit_group;" ::: "memory");
    };

    // accumulators: 4 control points x 2 m-frags x 4
    float acc[NCP][2][4];
    #pragma unroll
    for (int c = 0; c < NCP; c++)
        #pragma unroll
        for (int mf = 0; mf < 2; mf++)
            #pragma unroll
            for (int r = 0; r < 4; r++) acc[c][mf][r] = 0.f;

    fill(0, 0);      // prologue: chunk 0 -> stage 0

    for (int kc = 0; kc < NCHUNK; kc++) {
        const int cur = kc & 1;
        // chunk kc was issued one full iteration ago (or prologue)
        asm volatile("cp.async.wait_group 0;" ::: "memory");
        __syncthreads();   // makes all threads' fills visible + guards stage reuse

        // fill the OTHER stage (last read in iter kc-1; safe after the barrier)
        if (kc + 1 < NCHUNK) fill(cur ^ 1, kc + 1);

        const uint32_t sS = sbase + cur * STAGE_B;

        #pragma unroll
        for (int kp = 0; kp < 2; kp++) {               // two k32 halves
            const uint32_t ko = kp * 64;               // byte offset
            // B fragments for this k32: one x4 per (c, h/l)
            uint32_t bh[NCP][4], bl[NCP][4];           // [2*ks + 0..1]
            #pragma unroll
            for (int c = 0; c < NCP; c++) {
                uint32_t rb = (wn * 8) * ROWB + b_lane + ko;
                ldsm4(bh[c], sS + B_OFF + (2 * c) * B_PLANE + rb);
                ldsm4(bl[c], sS + B_OFF + (2 * c + 1) * B_PLANE + rb);
            }
            #pragma unroll
            for (int ks = 0; ks < 2; ks++) {           // k16 steps
                uint32_t ah[2][4], al[2][4];
                #pragma unroll
                for (int mf = 0; mf < 2; mf++) {
                    uint32_t ra = (wm * 32 + mf * 16) * ROWB + a_lane + ko + ks * 32;
                    ldsm4(ah[mf], sS + ra);
                    ldsm4(al[mf], sS + A_PLANE + ra);
                }
                #pragma unroll
                for (int term = 0; term < 3; term++) {
                    #pragma unroll
                    for (int c = 0; c < NCP; c++) {
                        #pragma unroll
                        for (int mf = 0; mf < 2; mf++) {
                            const uint32_t* af = (term == 2) ? al[mf] : ah[mf];
                            const uint32_t* bf = (term == 1) ? &bl[c][2 * ks]
                                                             : &bh[c][2 * ks];
                            mma16816(acc[c][mf], af, bf);
                        }
                    }
                }
            }
        }
    }

    // ---- epilogue: blend with coef + bias, store 64x32 tile ----
    #pragma unroll
    for (int mf = 0; mf < 2; mf++) {
        const int rl0  = wm * 32 + mf * 16 + g;
        const int row0 = mx * 64 + rl0;
        const int cl   = wn * 8 + 2 * t;
        float r0 = 0.f, r1 = 0.f, r2 = 0.f, r3 = 0.f;
        #pragma unroll
        for (int c = 0; c < NCP; c++) {
            float cc0 = coef_s[c][rl0];
            float cc8 = coef_s[c][rl0 + 8];
            float b0  = bias_s[c][cl];
            float b1  = bias_s[c][cl + 1];
            r0 = fmaf(cc0, acc[c][mf][0] + b0, r0);
            r1 = fmaf(cc0, acc[c][mf][1] + b1, r1);
            r2 = fmaf(cc8, acc[c][mf][2] + b0, r2);
            r3 = fmaf(cc8, acc[c][mf][3] + b1, r3);
        }
        int col = ny * 32 + cl;
        *(float2*)(out + (size_t)row0 * OUTF + col)       = make_float2(r0, r1);
        *(float2*)(out + (size_t)(row0 + 8) * OUTF + col) = make_float2(r2, r3);
    }
}

// ---------------- launch -------------------------------------------------------
extern "C" void kernel_launch(void* const* d_in, const int* in_sizes, int n_in,
                              void* d_out, int out_size) {
    const float* input   = (const float*)d_in[0];   // [1024,512]
    const float* phase   = (const float*)d_in[1];   // [1024]
    const float* weights = (const float*)d_in[2];   // [4,512,512]
    const float* biases  = (const float*)d_in[3];   // [4,512]
    float* out = (float*)d_out;                     // [1024,512]

    cudaFuncSetAttribute(fused_gemm,
                         cudaFuncAttributeMaxDynamicSharedMemorySize, SMEM_DYN);

    convert_kernel<<<1536, 256>>>(input, weights);

    dim3 grid(BATCH / 64, OUTF / 32);               // (16,16) = 256 CTAs
    fused_gemm<<<grid, 256, SMEM_DYN>>>(phase, biases, out);
}

// round 12
// speedup vs baseline: 1.3129x; 1.0767x over previous
#include <cuda_runtime.h>
#include <cuda_bf16.h>
#include <cstdint>

// ----------------------------------------------------------------------------
// PhaseLinear, 2 kernels:
//  1) convert: fp32 X,W -> bf16 hi/lo planes in __device__ scratch
//  2) fused gemm, WARP-SPECIALIZED: 8 compute warps + 4 producer warps.
//     Producers: cp.async fills + mbarrier full-arrive. Consumers: mbarrier
//     full-wait -> ldmatrix -> mma.sync bf16 (3-term hi/lo comp) -> empty-arrive.
//     No __syncthreads in the mainloop. CTA tile 64x64, BK=64, 2 stages.
// ----------------------------------------------------------------------------

#define BATCH 1024
#define INF   512
#define OUTF  512
#define NCP   4
#define NCAT  (NCP * OUTF)          // 2048

__device__ __nv_bfloat16 g_Xh[BATCH * INF], g_Xl[BATCH * INF];   // 1 MB each
__device__ __nv_bfloat16 g_Wh[NCAT * INF],  g_Wl[NCAT * INF];    // 2 MB each

// ---------------- helpers ----------------------------------------------------
__device__ __forceinline__ uint32_t smem_u32(const void* p) {
    uint32_t a;
    asm("{ .reg .u64 t; cvta.to.shared.u64 t, %1; cvt.u32.u64 %0, t; }"
        : "=r"(a) : "l"(p));
    return a;
}
__device__ __forceinline__ void split_pair(float x, float y, uint32_t& h, uint32_t& l) {
    asm("cvt.rn.bf16x2.f32 %0, %1, %2;" : "=r"(h) : "f"(y), "f"(x));  // {hi=y, lo=x}
    float hx = __uint_as_float(h << 16);
    float hy = __uint_as_float(h & 0xFFFF0000u);
    float rx = x - hx, ry = y - hy;
    asm("cvt.rn.bf16x2.f32 %0, %1, %2;" : "=r"(l) : "f"(ry), "f"(rx));
}
__device__ __forceinline__ void mma16816(float* d, const uint32_t* a, const uint32_t* b) {
    asm volatile(
        "mma.sync.aligned.m16n8k16.row.col.f32.bf16.bf16.f32 "
        "{%0,%1,%2,%3}, {%4,%5,%6,%7}, {%8,%9}, {%0,%1,%2,%3};"
        : "+f"(d[0]), "+f"(d[1]), "+f"(d[2]), "+f"(d[3])
        : "r"(a[0]), "r"(a[1]), "r"(a[2]), "r"(a[3]), "r"(b[0]), "r"(b[1]));
}
__device__ __forceinline__ void ldsm4(uint32_t* r, uint32_t addr) {
    asm volatile("ldmatrix.sync.aligned.m8n8.x4.shared.b16 {%0,%1,%2,%3}, [%4];"
        : "=r"(r[0]), "=r"(r[1]), "=r"(r[2]), "=r"(r[3]) : "r"(addr));
}
__device__ __forceinline__ void cpasync16(uint32_t dst, const void* src) {
    asm volatile("cp.async.cg.shared.global [%0], [%1], 16;" :: "r"(dst), "l"(src));
}

#define MBARRIER_INIT(mbar, cnt) \
    asm volatile("mbarrier.init.shared.b64 [%0], %1;" \
                 :: "r"((uint32_t)(mbar)), "r"((uint32_t)(cnt)) : "memory")
#define MBARRIER_ARRIVE(mbar) \
    asm volatile("mbarrier.arrive.shared.b64 _, [%0];" \
                 :: "r"((uint32_t)(mbar)) : "memory")
#define MBARRIER_WAIT_PARITY(mbar_smem_addr, phase_parity) do { \
    uint32_t _mbar = (uint32_t)(mbar_smem_addr); \
    uint32_t _parity = (uint32_t)(phase_parity); \
    uint32_t _done; \
    asm volatile("{\n\t.reg .pred p;\n\t" \
        "mbarrier.try_wait.parity.acquire.cta.shared::cta.b64 p, [%1], %2;\n\t" \
        "selp.b32 %0, 1, 0, p;\n\t}" \
        : "=r"(_done) : "r"(_mbar), "r"(_parity) : "memory"); \
    if (!_done) { \
        asm volatile("{\n\t.reg .pred P1;\n\t" \
            "WAIT_LOOP_%=:\n\t" \
            "mbarrier.try_wait.parity.acquire.cta.shared::cta.b64 P1, [%0], %1, 0x989680;\n\t" \
            "@P1 bra.uni WAIT_DONE_%=;\n\t" \
            "bra.uni WAIT_LOOP_%=;\n\t" \
            "WAIT_DONE_%=:\n\t}" \
            :: "r"(_mbar), "r"(_parity) : "memory"); \
    } \
} while (0)

// ---------------- 1) convert --------------------------------------------------
__global__ void convert_kernel(const float* __restrict__ X, const float* __restrict__ W) {
    int i = blockIdx.x * blockDim.x + threadIdx.x;     // float4 index
    const int NX = BATCH * INF / 4;                    // 131072
    const int NW = NCAT * INF / 4;                     // 262144
    float4 v; uint2* dh; uint2* dl;
    if (i < NX) {
        v = ((const float4*)X)[i];
        dh = (uint2*)g_Xh + i; dl = (uint2*)g_Xl + i;
    } else {
        int j = i - NX;
        if (j >= NW) return;
        v = ((const float4*)W)[j];
        dh = (uint2*)g_Wh + j; dl = (uint2*)g_Wl + j;
    }
    uint2 hp, lp;
    split_pair(v.x, v.y, hp.x, lp.x);
    split_pair(v.z, v.w, hp.y, lp.y);
    *dh = hp; *dl = lp;
}

// ---------------- 2) fused GEMM (warp-specialized) -----------------------------
// CTA tile 64(m) x 64(n), BK=64, 8 K-chunks, 2 stages.
// Stage: Ah[64x144B] @0, Al @9216, B planes (64x144B) q=2c+(h/l) @18432+q*9216.
#define ROWB     144
#define A_PLANE  9216
#define B_PLANE  9216
#define B_OFF    18432
#define STAGE_B  92160
#define NCHUNK   (INF / 64)     // 8
#define SMEM_DYN (2 * STAGE_B)  // 184320

#define NTHREADS 384            // 8 compute warps + 4 producer warps

__global__ void __launch_bounds__(NTHREADS, 1)
fused_gemm(const float* __restrict__ phase, const float* __restrict__ biases,
           float* __restrict__ out) {
    extern __shared__ __align__(128) char smem[];
    const uint32_t sbase = smem_u32(smem);
    __shared__ __align__(8) unsigned long long s_full[2], s_empty[2];
    __shared__ float coef_s[NCP][64];
    __shared__ float bias_s[NCP][64];

    const int tid  = threadIdx.x;
    const int wid  = tid >> 5;
    const int lane = tid & 31;
    const int mx   = blockIdx.x;   // 0..15 (64 batch rows)
    const int ny   = blockIdx.y;   // 0..7  (64 out cols)

    const uint32_t full0  = smem_u32(&s_full[0]);
    const uint32_t full1  = smem_u32(&s_full[1]);
    const uint32_t empty0 = smem_u32(&s_empty[0]);
    const uint32_t empty1 = smem_u32(&s_empty[1]);

    if (tid == 0) {
        MBARRIER_INIT(full0, 128);   // producer threads
        MBARRIER_INIT(full1, 128);
        MBARRIER_INIT(empty0, 256);  // consumer threads
        MBARRIER_INIT(empty1, 256);
    }
    // ---- coef + bias tables ----
    if (tid < 64) {
        const float PI = 3.14159265358979323846f;
        float p = phase[mx * 64 + tid];
        float tt = (p < 1.5f * PI) ? (p / (1.5f * PI)) : ((p - 0.5f * PI) / (1.5f * PI));
        float t2 = tt * tt, t3 = t2 * tt;
        coef_s[0][tid] = t3 - 0.5f * t2;
        coef_s[1][tid] = 1.0f - 2.5f * t3;
        coef_s[2][tid] = 0.5f * t2 + 2.0f * t3;
        coef_s[3][tid] = -0.5f * t3;
    } else if (tid < 128) {
        int j = tid - 64;
        #pragma unroll
        for (int c = 0; c < NCP; c++)
            bias_s[c][j] = biases[c * OUTF + ny * 64 + j];
    }
    __syncthreads();   // barriers + tables visible; only sync in the kernel

    if (wid >= 8) {
        // ================= PRODUCER (4 warps, 128 threads) =================
        const int ptid = tid - 256;    // 0..127
        const __nv_bfloat16* xh = g_Xh + (size_t)(mx * 64) * INF;
        const __nv_bfloat16* xl = g_Xl + (size_t)(mx * 64) * INF;

        int pstage = 0, pphase = 1;    // flipped phase: first 2 empty-waits pass
        for (int kc = 0; kc < NCHUNK; kc++) {
            MBARRIER_WAIT_PARITY(pstage ? empty1 : empty0, pphase);
            // fill stage: 5120 cp.async x 16B, 40 per thread
            #pragma unroll
            for (int i = 0; i < 40; i++) {
                int u = i * 128 + ptid;          // 0..5119
                uint32_t dst; const __nv_bfloat16* src;
                if (u < 1024) {                  // A planes: 2 x 64 rows x 8 segs
                    int pl  = u >> 9;
                    int r   = (u >> 3) & 63;
                    int seg = u & 7;
                    src = (pl ? xl : xh) + (size_t)r * INF + kc * 64 + seg * 8;
                    dst = sbase + pstage * STAGE_B + pl * A_PLANE + r * ROWB + seg * 16;
                } else {                         // B planes: 8 x 64 rows x 8 segs
                    int v   = u - 1024;
                    int q   = v >> 9;            // 0..7 = 2c + (h/l)
                    int r   = (v >> 3) & 63;
                    int seg = v & 7;
                    int c   = q >> 1;
                    const __nv_bfloat16* wb = (q & 1) ? g_Wl : g_Wh;
                    src = wb + (size_t)(c * OUTF + ny * 64 + r) * INF + kc * 64 + seg * 8;
                    dst = sbase + pstage * STAGE_B + B_OFF + q * B_PLANE + r * ROWB + seg * 16;
                }
                cpasync16(dst, src);
            }
            asm volatile("cp.async.commit_group;" ::: "memory");
            asm volatile("cp.async.wait_group 0;" ::: "memory");
            MBARRIER_ARRIVE(pstage ? full1 : full0);
            pstage ^= 1;
            if (pstage == 0) pphase ^= 1;
        }
        return;
    }

    // ================= CONSUMER (8 warps, 256 threads) =================
    const int g  = lane >> 2;
    const int t  = lane & 3;
    const int wm = wid & 1;       // m-half: wm*32
    const int wn = wid >> 1;      // n-quarter: wn*16

    // ldmatrix lane addresses (byte offsets within a plane)
    const uint32_t a_lane = (((lane >> 3) & 1) * 8 + (lane & 7)) * ROWB
                          + (lane >> 4) * 16;
    // B x4: m0 = n0-7/k0-7, m1 = n8-15/k0-7, m2 = n0-7/k8-15, m3 = n8-15/k8-15
    const uint32_t b_lane = ((lane & 7) + ((lane >> 3) & 1) * 8) * ROWB
                          + ((lane >> 4) & 1) * 16;

    float acc[NCP][2][2][4];
    #pragma unroll
    for (int c = 0; c < NCP; c++)
        #pragma unroll
        for (int mf = 0; mf < 2; mf++)
            #pragma unroll
            for (int nf = 0; nf < 2; nf++)
                #pragma unroll
                for (int r = 0; r < 4; r++) acc[c][mf][nf][r] = 0.f;

    int cstage = 0, cphase = 0;
    for (int kc = 0; kc < NCHUNK; kc++) {
        MBARRIER_WAIT_PARITY(cstage ? full1 : full0, cphase);
        const uint32_t sS = sbase + cstage * STAGE_B;

        #pragma unroll
        for (int ks = 0; ks < 4; ks++) {           // 4 x k16
            const uint32_t ko = ks * 32;           // bytes
            uint32_t ah[2][4], al[2][4];
            #pragma unroll
            for (int mf = 0; mf < 2; mf++) {
                uint32_t ra = (wm * 32 + mf * 16) * ROWB + a_lane + ko;
                ldsm4(ah[mf], sS + ra);
                ldsm4(al[mf], sS + A_PLANE + ra);
            }
            #pragma unroll
            for (int c = 0; c < NCP; c++) {
                const uint32_t rb = (wn * 16) * ROWB + b_lane + ko;
                uint32_t tH[4], tL[4];
                ldsm4(tH, sS + B_OFF + (2 * c) * B_PLANE + rb);
                ldsm4(tL, sS + B_OFF + (2 * c + 1) * B_PLANE + rb);
                uint32_t bh[2][2] = {{tH[0], tH[2]}, {tH[1], tH[3]}};
                uint32_t bl[2][2] = {{tL[0], tL[2]}, {tL[1], tL[3]}};
                #pragma unroll
                for (int mf = 0; mf < 2; mf++)
                    #pragma unroll
                    for (int nf = 0; nf < 2; nf++) {
                        mma16816(acc[c][mf][nf], ah[mf], bh[nf]);
                        mma16816(acc[c][mf][nf], ah[mf], bl[nf]);
                        mma16816(acc[c][mf][nf], al[mf], bh[nf]);
                    }
            }
        }
        MBARRIER_ARRIVE(cstage ? empty1 : empty0);
        cstage ^= 1;
        if (cstage == 0) cphase ^= 1;
    }

    // ---- epilogue: blend with coef + bias, store 64x64 tile ----
    #pragma unroll
    for (int mf = 0; mf < 2; mf++) {
        const int rl0  = wm * 32 + mf * 16 + g;
        const int row0 = mx * 64 + rl0;
        #pragma unroll
        for (int nf = 0; nf < 2; nf++) {
            const int cl = wn * 16 + nf * 8 + 2 * t;
            float r0 = 0.f, r1 = 0.f, r2 = 0.f, r3 = 0.f;
            #pragma unroll
            for (int c = 0; c < NCP; c++) {
                float cc0 = coef_s[c][rl0];
                float cc8 = coef_s[c][rl0 + 8];
                float b0  = bias_s[c][cl];
                float b1  = bias_s[c][cl + 1];
                r0 = fmaf(cc0, acc[c][mf][nf][0] + b0, r0);
                r1 = fmaf(cc0, acc[c][mf][nf][1] + b1, r1);
                r2 = fmaf(cc8, acc[c][mf][nf][2] + b0, r2);
                r3 = fmaf(cc8, acc[c][mf][nf][3] + b1, r3);
            }
            int col = ny * 64 + cl;
            *(float2*)(out + (size_t)row0 * OUTF + col)       = make_float2(r0, r1);
            *(float2*)(out + (size_t)(row0 + 8) * OUTF + col) = make_float2(r2, r3);
        }
    }
}

// ---------------- launch -------------------------------------------------------
extern "C" void kernel_launch(void* const* d_in, const int* in_sizes, int n_in,
                              void* d_out, int out_size) {
    const float* input   = (const float*)d_in[0];   // [1024,512]
    const float* phase   = (const float*)d_in[1];   // [1024]
    const float* weights = (const float*)d_in[2];   // [4,512,512]
    const float* biases  = (const float*)d_in[3];   // [4,512]
    float* out = (float*)d_out;                     // [1024,512]

    cudaFuncSetAttribute(fused_gemm,
                         cudaFuncAttributeMaxDynamicSharedMemorySize, SMEM_DYN);

    convert_kernel<<<1536, 256>>>(input, weights);

    dim3 grid(BATCH / 64, OUTF / 64);               // (16,8) = 128 CTAs
    fused_gemm<<<grid, NTHREADS, SMEM_DYN>>>(phase, biases, out);
}

// round 14
// speedup vs baseline: 1.3797x; 1.0509x over previous
#include <cuda_runtime.h>
#include <cuda_bf16.h>
#include <cstdint>

// ----------------------------------------------------------------------------
// PhaseLinear, SINGLE warp-specialized kernel (mma.sync bf16, 3-term hi/lo):
//   producers (4 warps): LDG fp32 -> bf16 hi/lo split -> STS planes
//   consumers (8 warps): mbarrier wait -> ldmatrix -> 192 MMA/warp/chunk
//   epilogue: in-register blend out = sum_c coef[b,c]*(acc_c + bias[c,o])
// CTA tile 64x64, BK=64, 2 stages, mbarrier full/empty ring.
// ----------------------------------------------------------------------------

#define BATCH 1024
#define INF   512
#define OUTF  512
#define NCP   4

// ---------------- helpers ----------------------------------------------------
__device__ __forceinline__ uint32_t smem_u32(const void* p) {
    uint32_t a;
    asm("{ .reg .u64 t; cvta.to.shared.u64 t, %1; cvt.u32.u64 %0, t; }"
        : "=r"(a) : "l"(p));
    return a;
}
__device__ __forceinline__ void split_pair(float x, float y, uint32_t& h, uint32_t& l) {
    asm("cvt.rn.bf16x2.f32 %0, %1, %2;" : "=r"(h) : "f"(y), "f"(x));  // {hi=y, lo=x}
    float hx = __uint_as_float(h << 16);
    float hy = __uint_as_float(h & 0xFFFF0000u);
    float rx = x - hx, ry = y - hy;
    asm("cvt.rn.bf16x2.f32 %0, %1, %2;" : "=r"(l) : "f"(ry), "f"(rx));
}
__device__ __forceinline__ void mma16816(float* d, const uint32_t* a, const uint32_t* b) {
    asm volatile(
        "mma.sync.aligned.m16n8k16.row.col.f32.bf16.bf16.f32 "
        "{%0,%1,%2,%3}, {%4,%5,%6,%7}, {%8,%9}, {%0,%1,%2,%3};"
        : "+f"(d[0]), "+f"(d[1]), "+f"(d[2]), "+f"(d[3])
        : "r"(a[0]), "r"(a[1]), "r"(a[2]), "r"(a[3]), "r"(b[0]), "r"(b[1]));
}
__device__ __forceinline__ void ldsm4(uint32_t* r, uint32_t addr) {
    asm volatile("ldmatrix.sync.aligned.m8n8.x4.shared.b16 {%0,%1,%2,%3}, [%4];"
        : "=r"(r[0]), "=r"(r[1]), "=r"(r[2]), "=r"(r[3]) : "r"(addr));
}

#define MBARRIER_INIT(mbar, cnt) \
    asm volatile("mbarrier.init.shared.b64 [%0], %1;" \
                 :: "r"((uint32_t)(mbar)), "r"((uint32_t)(cnt)) : "memory")
#define MBARRIER_ARRIVE(mbar) \
    asm volatile("mbarrier.arrive.shared.b64 _, [%0];" \
                 :: "r"((uint32_t)(mbar)) : "memory")
#define MBARRIER_WAIT_PARITY(mbar_smem_addr, phase_parity) do { \
    uint32_t _mbar = (uint32_t)(mbar_smem_addr); \
    uint32_t _parity = (uint32_t)(phase_parity); \
    uint32_t _done; \
    asm volatile("{\n\t.reg .pred p;\n\t" \
        "mbarrier.try_wait.parity.acquire.cta.shared::cta.b64 p, [%1], %2;\n\t" \
        "selp.b32 %0, 1, 0, p;\n\t}" \
        : "=r"(_done) : "r"(_mbar), "r"(_parity) : "memory"); \
    if (!_done) { \
        asm volatile("{\n\t.reg .pred P1;\n\t" \
            "WAIT_LOOP_%=:\n\t" \
            "mbarrier.try_wait.parity.acquire.cta.shared::cta.b64 P1, [%0], %1, 0x989680;\n\t" \
            "@P1 bra.uni WAIT_DONE_%=;\n\t" \
            "bra.uni WAIT_LOOP_%=;\n\t" \
            "WAIT_DONE_%=:\n\t}" \
            :: "r"(_mbar), "r"(_parity) : "memory"); \
    } \
} while (0)

// ---------------- fused kernel -------------------------------------------------
// CTA tile 64(m) x 64(n), BK=64, 8 K-chunks, 2 stages.
// Stage: Ah[64x144B] @0, Al @9216, B planes (64x144B) q=2c+(h/l) @18432+q*9216.
#define ROWB     144
#define A_PLANE  9216
#define B_PLANE  9216
#define B_OFF    18432
#define STAGE_B  92160
#define NCHUNK   (INF / 64)     // 8
#define SMEM_DYN (2 * STAGE_B)  // 184320

#define NTHREADS 384            // 8 consumer warps + 4 producer warps

__global__ void __launch_bounds__(NTHREADS, 1)
fused_gemm(const float* __restrict__ X, const float* __restrict__ phase,
           const float* __restrict__ W, const float* __restrict__ biases,
           float* __restrict__ out) {
    extern __shared__ __align__(128) char smem[];
    const uint32_t sbase = smem_u32(smem);
    __shared__ __align__(8) unsigned long long s_full[2], s_empty[2];
    __shared__ float coef_s[NCP][64];
    __shared__ float bias_s[NCP][64];

    const int tid  = threadIdx.x;
    const int wid  = tid >> 5;
    const int lane = tid & 31;
    const int mx   = blockIdx.x;   // 0..15 (64 batch rows)
    const int ny   = blockIdx.y;   // 0..7  (64 out cols)

    const uint32_t full0  = smem_u32(&s_full[0]);
    const uint32_t full1  = smem_u32(&s_full[1]);
    const uint32_t empty0 = smem_u32(&s_empty[0]);
    const uint32_t empty1 = smem_u32(&s_empty[1]);

    if (tid == 0) {
        MBARRIER_INIT(full0, 128);   // producer threads
        MBARRIER_INIT(full1, 128);
        MBARRIER_INIT(empty0, 256);  // consumer threads
        MBARRIER_INIT(empty1, 256);
    }
    // ---- coef + bias tables ----
    if (tid < 64) {
        const float PI = 3.14159265358979323846f;
        float p = phase[mx * 64 + tid];
        float tt = (p < 1.5f * PI) ? (p / (1.5f * PI)) : ((p - 0.5f * PI) / (1.5f * PI));
        float t2 = tt * tt, t3 = t2 * tt;
        coef_s[0][tid] = t3 - 0.5f * t2;
        coef_s[1][tid] = 1.0f - 2.5f * t3;
        coef_s[2][tid] = 0.5f * t2 + 2.0f * t3;
        coef_s[3][tid] = -0.5f * t3;
    } else if (tid < 128) {
        int j = tid - 64;
        #pragma unroll
        for (int c = 0; c < NCP; c++)
            bias_s[c][j] = biases[c * OUTF + ny * 64 + j];
    }
    __syncthreads();   // barriers + tables visible; only block-sync in kernel

    if (wid >= 8) {
        // ================= PRODUCER (4 warps, 128 threads) =================
        // Per chunk: 5120 float4 fp32 loads -> hi/lo split -> STS, 40/thread.
        const int ptid = tid - 256;    // 0..127
        const int pr   = ptid >> 4;    // row sub-index 0..7
        const int pf   = ptid & 15;    // float4-in-row 0..15

        int pstage = 0, pphase = 1;    // flipped: first 2 empty-waits pass
        for (int kc = 0; kc < NCHUNK; kc++) {
            MBARRIER_WAIT_PARITY(pstage ? empty1 : empty0, pphase);
            const uint32_t sb = sbase + pstage * STAGE_B;
            // A: 1024 float4 = 64 rows x 16 f4  (i = 0..7)
            #pragma unroll
            for (int i = 0; i < 8; i++) {
                int r = i * 8 + pr;                     // 0..63
                float4 v = *(const float4*)(X + (size_t)(mx * 64 + r) * INF
                                            + kc * 64 + pf * 4);
                uint32_t h0, l0, h1, l1;
                split_pair(v.x, v.y, h0, l0);
                split_pair(v.z, v.w, h1, l1);
                uint32_t off = sb + r * ROWB + pf * 8;
                *(uint2*)(smem + (off - sbase))            = make_uint2(h0, h1);
                *(uint2*)(smem + (off - sbase) + A_PLANE)  = make_uint2(l0, l1);
            }
            // B: 4096 float4 = 4c x 64 rows x 16 f4  (i = 0..31)
            #pragma unroll
            for (int i = 0; i < 32; i++) {
                int c = i >> 3;                         // 0..3
                int r = (i & 7) * 8 + pr;               // 0..63
                float4 v = *(const float4*)(W + (size_t)(c * OUTF + ny * 64 + r) * INF
                                            + kc * 64 + pf * 4);
                uint32_t h0, l0, h1, l1;
                split_pair(v.x, v.y, h0, l0);
                split_pair(v.z, v.w, h1, l1);
                uint32_t off = sb + B_OFF + (2 * c) * B_PLANE + r * ROWB + pf * 8;
                *(uint2*)(smem + (off - sbase))            = make_uint2(h0, h1);
                *(uint2*)(smem + (off - sbase) + B_PLANE)  = make_uint2(l0, l1);
            }
            MBARRIER_ARRIVE(pstage ? full1 : full0);   // release: STS visible
            pstage ^= 1;
            if (pstage == 0) pphase ^= 1;
        }
        return;
    }

    // ================= CONSUMER (8 warps, 256 threads) =================
    const int g  = lane >> 2;
    const int t  = lane & 3;
    const int wm = wid & 1;       // m-half: wm*32
    const int wn = wid >> 1;      // n-quarter: wn*16

    const uint32_t a_lane = (((lane >> 3) & 1) * 8 + (lane & 7)) * ROWB
                          + (lane >> 4) * 16;
    // B x4: m0 = n0-7/k0-7, m1 = n8-15/k0-7, m2 = n0-7/k8-15, m3 = n8-15/k8-15
    const uint32_t b_lane = ((lane & 7) + ((lane >> 3) & 1) * 8) * ROWB
                          + ((lane >> 4) & 1) * 16;

    float acc[NCP][2][2][4];
    #pragma unroll
    for (int c = 0; c < NCP; c++)
        #pragma unroll
        for (int mf = 0; mf < 2; mf++)
            #pragma unroll
            for (int nf = 0; nf < 2; nf++)
                #pragma unroll
                for (int r = 0; r < 4; r++) acc[c][mf][nf][r] = 0.f;

    int cstage = 0, cphase = 0;
    for (int kc = 0; kc < NCHUNK; kc++) {
        MBARRIER_WAIT_PARITY(cstage ? full1 : full0, cphase);
        const uint32_t sS = sbase + cstage * STAGE_B;

        #pragma unroll
        for (int ks = 0; ks < 4; ks++) {           // 4 x k16
            const uint32_t ko = ks * 32;           // bytes
            // ---- batch ALL fragment loads for this k16 first ----
            uint32_t ah[2][4], al[2][4];
            #pragma unroll
            for (int mf = 0; mf < 2; mf++) {
                uint32_t ra = (wm * 32 + mf * 16) * ROWB + a_lane + ko;
                ldsm4(ah[mf], sS + ra);
                ldsm4(al[mf], sS + A_PLANE + ra);
            }
            uint32_t tH[NCP][4], tL[NCP][4];
            #pragma unroll
            for (int c = 0; c < NCP; c++) {
                const uint32_t rb = (wn * 16) * ROWB + b_lane + ko;
                ldsm4(tH[c], sS + B_OFF + (2 * c) * B_PLANE + rb);
                ldsm4(tL[c], sS + B_OFF + (2 * c + 1) * B_PLANE + rb);
            }
            // ---- then the 48 MMAs ----
            #pragma unroll
            for (int c = 0; c < NCP; c++) {
                uint32_t bh[2][2] = {{tH[c][0], tH[c][2]}, {tH[c][1], tH[c][3]}};
                uint32_t bl[2][2] = {{tL[c][0], tL[c][2]}, {tL[c][1], tL[c][3]}};
                #pragma unroll
                for (int mf = 0; mf < 2; mf++)
                    #pragma unroll
                    for (int nf = 0; nf < 2; nf++) {
                        mma16816(acc[c][mf][nf], ah[mf], bh[nf]);
                        mma16816(acc[c][mf][nf], ah[mf], bl[nf]);
                        mma16816(acc[c][mf][nf], al[mf], bh[nf]);
                    }
            }
        }
        MBARRIER_ARRIVE(cstage ? empty1 : empty0);
        cstage ^= 1;
        if (cstage == 0) cphase ^= 1;
    }

    // ---- epilogue: blend with coef + bias, store 64x64 tile ----
    #pragma unroll
    for (int mf = 0; mf < 2; mf++) {
        const int rl0  = wm * 32 + mf * 16 + g;
        const int row0 = mx * 64 + rl0;
        #pragma unroll
        for (int nf = 0; nf < 2; nf++) {
            const int cl = wn * 16 + nf * 8 + 2 * t;
            float r0 = 0.f, r1 = 0.f, r2 = 0.f, r3 = 0.f;
            #pragma unroll
            for (int c = 0; c < NCP; c++) {
                float cc0 = coef_s[c][rl0];
                float cc8 = coef_s[c][rl0 + 8];
                float b0  = bias_s[c][cl];
                float b1  = bias_s[c][cl + 1];
                r0 = fmaf(cc0, acc[c][mf][nf][0] + b0, r0);
                r1 = fmaf(cc0, acc[c][mf][nf][1] + b1, r1);
                r2 = fmaf(cc8, acc[c][mf][nf][2] + b0, r2);
                r3 = fmaf(cc8, acc[c][mf][nf][3] + b1, r3);
            }
            int col = ny * 64 + cl;
            *(float2*)(out + (size_t)row0 * OUTF + col)       = make_float2(r0, r1);
            *(float2*)(out + (size_t)(row0 + 8) * OUTF + col) = make_float2(r2, r3);
        }
    }
}

// ---------------- launch -------------------------------------------------------
extern "C" void kernel_launch(void* const* d_in, const int* in_sizes, int n_in,
                              void* d_out, int out_size) {
    const float* input   = (const float*)d_in[0];   // [1024,512]
    const float* phase   = (const float*)d_in[1];   // [1024]
    const float* weights = (const float*)d_in[2];   // [4,512,512]
    const float* biases  = (const float*)d_in[3];   // [4,512]
    float* out = (float*)d_out;                     // [1024,512]

    cudaFuncSetAttribute(fused_gemm,
                         cudaFuncAttributeMaxDynamicSharedMemorySize, SMEM_DYN);

    dim3 grid(BATCH / 64, OUTF / 64);               // (16,8) = 128 CTAs
    fused_gemm<<<grid, NTHREADS, SMEM_DYN>>>(input, phase, weights, biases, out);
}